// round 2
// baseline (speedup 1.0000x reference)
#include <cuda_runtime.h>
#include <cuda_bf16.h>
#include <cstdint>

#define B_   2
#define DIN  4096
#define LL   4096
#define NN   16
#define RR   128
#define KOUT 160   // R + 2N

// ---------------- scratch (static __device__ per allocation rules) ----------
__device__ float g_dt[B_ * RR * LL];          // dt_low, layout [b][r][l]       (4 MB)
__device__ float g_bc[B_ * LL * 32];          // B/C transposed [b][l][32]      (1 MB)
__device__ float g_delta[(size_t)B_ * DIN * LL]; // softplus'd delta [b][d][l] (128 MB)

// ---------------------------------------------------------------------------
// GEMM1: xd[b,k,l] = sum_d x[b,d,l] * W1[k,d];  k in [0,160)
//   k < 128  -> g_dt[b][k][l]
//   k >= 128 -> g_bc[b][l][k-128]   (transposed for scan coalescing)
// Tile: 32(k) x 128(l) x 32(d), 256 threads, 4x4 per thread.
// ---------------------------------------------------------------------------
__global__ void gemm1_kernel(const float* __restrict__ x,
                             const float* __restrict__ w1)
{
    const int b  = blockIdx.z;
    const int k0 = blockIdx.y * 32;
    const int l0 = blockIdx.x * 128;
    const float* xb = x + (size_t)b * DIN * LL;

    __shared__ float As[32][33];   // w1 tile [k][d]
    __shared__ float Bs[32][128];  // x  tile [d][l]

    const int tid = threadIdx.x;
    const int ty  = tid >> 5;      // 0..7  -> k sub-tile
    const int tx  = tid & 31;      // 0..31 -> l sub-tile

    float acc[4][4];
#pragma unroll
    for (int i = 0; i < 4; i++)
#pragma unroll
        for (int j = 0; j < 4; j++) acc[i][j] = 0.f;

    for (int d0 = 0; d0 < DIN; d0 += 32) {
        // load A tile: 32 rows x 32 cols, one float4 per thread
        {
            const int r  = tid >> 3;         // 0..31
            const int c4 = (tid & 7) * 4;    // 0..28
            float4 v = *(const float4*)&w1[(size_t)(k0 + r) * DIN + d0 + c4];
            As[r][c4 + 0] = v.x; As[r][c4 + 1] = v.y;
            As[r][c4 + 2] = v.z; As[r][c4 + 3] = v.w;
        }
        // load B tile: 32 rows x 128 cols, 4 float4 per thread
#pragma unroll
        for (int i = 0; i < 4; i++) {
            const int lin = tid + i * 256;
            const int rr  = lin >> 5;
            const int cc  = (lin & 31) * 4;
            float4 v = *(const float4*)&xb[(size_t)(d0 + rr) * LL + l0 + cc];
            *(float4*)&Bs[rr][cc] = v;
        }
        __syncthreads();

#pragma unroll
        for (int dd = 0; dd < 32; dd++) {
            float a[4];
#pragma unroll
            for (int i = 0; i < 4; i++) a[i] = As[ty * 4 + i][dd];
            float4 bv = *(const float4*)&Bs[dd][tx * 4];
            float bb[4] = {bv.x, bv.y, bv.z, bv.w};
#pragma unroll
            for (int i = 0; i < 4; i++)
#pragma unroll
                for (int j = 0; j < 4; j++)
                    acc[i][j] = fmaf(a[i], bb[j], acc[i][j]);
        }
        __syncthreads();
    }

#pragma unroll
    for (int i = 0; i < 4; i++) {
        const int k = k0 + ty * 4 + i;
#pragma unroll
        for (int j = 0; j < 4; j++) {
            const int l = l0 + tx * 4 + j;
            const float v = acc[i][j];
            if (k < RR)
                g_dt[((size_t)b * RR + k) * LL + l] = v;
            else
                g_bc[((size_t)b * LL + l) * 32 + (k - RR)] = v;
        }
    }
}

// ---------------------------------------------------------------------------
// GEMM2 + softplus: delta[b,d,l] = softplus( sum_r W2[d,r]*dt[b,r,l] + bias[d] )
// Tile: 32(d) x 128(l) x 32(r), 256 threads, 4x4 per thread. K = 128 -> 4 iters.
// ---------------------------------------------------------------------------
__global__ void gemm2_kernel(const float* __restrict__ w2,
                             const float* __restrict__ bias)
{
    const int b  = blockIdx.z;
    const int d0 = blockIdx.y * 32;
    const int l0 = blockIdx.x * 128;

    __shared__ float As[32][33];   // w2 tile [d][r]
    __shared__ float Bs[32][128];  // dt tile [r][l]

    const int tid = threadIdx.x;
    const int ty  = tid >> 5;
    const int tx  = tid & 31;

    float acc[4][4];
#pragma unroll
    for (int i = 0; i < 4; i++)
#pragma unroll
        for (int j = 0; j < 4; j++) acc[i][j] = 0.f;

    for (int r0 = 0; r0 < RR; r0 += 32) {
        {
            const int r  = tid >> 3;
            const int c4 = (tid & 7) * 4;
            float4 v = *(const float4*)&w2[(size_t)(d0 + r) * RR + r0 + c4];
            As[r][c4 + 0] = v.x; As[r][c4 + 1] = v.y;
            As[r][c4 + 2] = v.z; As[r][c4 + 3] = v.w;
        }
#pragma unroll
        for (int i = 0; i < 4; i++) {
            const int lin = tid + i * 256;
            const int rr  = lin >> 5;
            const int cc  = (lin & 31) * 4;
            float4 v = *(const float4*)&g_dt[((size_t)b * RR + r0 + rr) * LL + l0 + cc];
            *(float4*)&Bs[rr][cc] = v;
        }
        __syncthreads();

#pragma unroll
        for (int dd = 0; dd < 32; dd++) {
            float a[4];
#pragma unroll
            for (int i = 0; i < 4; i++) a[i] = As[ty * 4 + i][dd];
            float4 bv = *(const float4*)&Bs[dd][tx * 4];
            float bb[4] = {bv.x, bv.y, bv.z, bv.w};
#pragma unroll
            for (int i = 0; i < 4; i++)
#pragma unroll
                for (int j = 0; j < 4; j++)
                    acc[i][j] = fmaf(a[i], bb[j], acc[i][j]);
        }
        __syncthreads();
    }

#pragma unroll
    for (int i = 0; i < 4; i++) {
        const int d = d0 + ty * 4 + i;
        const float bi = bias[d];
#pragma unroll
        for (int j = 0; j < 4; j++) {
            const int l = l0 + tx * 4 + j;
            const float z  = acc[i][j] + bi;
            // numerically stable softplus
            const float sp = fmaxf(z, 0.f) + log1pf(expf(-fabsf(z)));
            g_delta[((size_t)b * DIN + d) * LL + l] = sp;
        }
    }
}

// ---------------------------------------------------------------------------
// Scan: one 16-lane group per (b,d). Lane n owns state h[n].
//   h = h*exp(delta*A[d,n]) + (delta*u)*B[n,l];  y[l] = sum_n h*C[n,l] + u*D[d]
// Unroll L by 4, float4 loads for delta/u, float4 store for y.
// ---------------------------------------------------------------------------
__global__ void scan_kernel(const float* __restrict__ x,
                            const float* __restrict__ A_log,
                            const float* __restrict__ Dvec,
                            float* __restrict__ y)
{
    const int gtid  = blockIdx.x * blockDim.x + threadIdx.x;
    const int group = gtid >> 4;          // (b,d) pair: 0..8191
    const int n     = gtid & 15;
    const int b     = group >> 12;        // /4096
    const int d     = group & 4095;

    const size_t base = ((size_t)b * DIN + d) * LL;
    const float  a    = -__expf(A_log[d * NN + n]);
    const float  Dd   = Dvec[d];
    const float* bcb  = g_bc + (size_t)b * LL * 32;

    float h = 0.f;
    for (int l0 = 0; l0 < LL; l0 += 4) {
        const float4 tz = *(const float4*)(g_delta + base + l0);
        const float4 uu = *(const float4*)(x + base + l0);
        const float tj[4] = {tz.x, tz.y, tz.z, tz.w};
        const float uj[4] = {uu.x, uu.y, uu.z, uu.w};
        float yv[4];
#pragma unroll
        for (int j = 0; j < 4; j++) {
            const float t  = tj[j];
            const float u  = uj[j];
            const float Bn = bcb[(size_t)(l0 + j) * 32 + n];
            const float Cn = bcb[(size_t)(l0 + j) * 32 + 16 + n];
            const float dA = __expf(t * a);
            h = fmaf(h, dA, (t * u) * Bn);
            float p = h * Cn;
            // reduce across the 16-lane group
            p += __shfl_xor_sync(0xffffffffu, p, 1);
            p += __shfl_xor_sync(0xffffffffu, p, 2);
            p += __shfl_xor_sync(0xffffffffu, p, 4);
            p += __shfl_xor_sync(0xffffffffu, p, 8);
            yv[j] = fmaf(u, Dd, p);
        }
        if (n == 0) {
            float4 o = {yv[0], yv[1], yv[2], yv[3]};
            *(float4*)(y + base + l0) = o;
        }
    }
}

// ---------------------------------------------------------------------------
extern "C" void kernel_launch(void* const* d_in, const int* in_sizes, int n_in,
                              void* d_out, int out_size)
{
    const float* x     = (const float*)d_in[0];  // (B, D, L)
    const float* A_log = (const float*)d_in[1];  // (D, N)
    const float* Dvec  = (const float*)d_in[2];  // (D,)
    const float* xpw   = (const float*)d_in[3];  // (160, D)
    const float* dtw   = (const float*)d_in[4];  // (D, R)
    const float* dtb   = (const float*)d_in[5];  // (D,)
    float* y = (float*)d_out;

    {
        dim3 grid(LL / 128, KOUT / 32, B_);   // 32 x 5 x 2
        gemm1_kernel<<<grid, 256>>>(x, xpw);
    }
    {
        dim3 grid(LL / 128, DIN / 32, B_);    // 32 x 128 x 2
        gemm2_kernel<<<grid, 256>>>(dtw, dtb);
    }
    {
        const int threads = 128;              // 8 groups per block
        const int blocks  = (B_ * DIN * NN) / threads; // 1024
        scan_kernel<<<blocks, threads>>>(x, A_log, Dvec, y);
    }
}

// round 4
// speedup vs baseline: 1.2990x; 1.2990x over previous
#include <cuda_runtime.h>
#include <cuda_bf16.h>
#include <cstdint>

#define B_   2
#define DIN  4096
#define LL   4096
#define NN   16
#define RR   128
#define KOUT 160   // R + 2N

// ---------------- scratch (static __device__ per allocation rules) ----------
__device__ float g_dt[B_ * RR * LL];             // dt_low [b][r][l]            (4 MB)
__device__ float g_bc[B_ * LL * 32];             // B/C transposed [b][l][32]   (1 MB)
__device__ float g_delta[(size_t)B_ * DIN * LL]; // softplus'd delta [b][d][l]  (128 MB)

// ---------------- helpers ---------------------------------------------------
__device__ __forceinline__ uint32_t f2tf(float f) {
    uint32_t u;
    asm("cvt.rna.tf32.f32 %0, %1;" : "=r"(u) : "f"(f));
    return u;
}

__device__ __forceinline__ void mma_tf32(float (&d)[4],
                                         uint32_t a0, uint32_t a1, uint32_t a2, uint32_t a3,
                                         uint32_t b0, uint32_t b1) {
    asm("mma.sync.aligned.m16n8k8.row.col.f32.tf32.tf32.f32 "
        "{%0,%1,%2,%3},{%4,%5,%6,%7},{%8,%9},{%0,%1,%2,%3};"
        : "+f"(d[0]), "+f"(d[1]), "+f"(d[2]), "+f"(d[3])
        : "r"(a0), "r"(a1), "r"(a2), "r"(a3), "r"(b0), "r"(b1));
}

__device__ __forceinline__ float softplus_fast(float z) {
    return fmaxf(z, 0.f) + __logf(1.f + __expf(-fabsf(z)));
}

// ---------------------------------------------------------------------------
// GEMM1 (tf32 TC): xd[b,k,l] = sum_d x[b,d,l] * W1[k,d]
// Block tile 32(M=k) x 256(N=l), K(d)-chunks of 32. 8 warps (2m x 4n),
// warp tile 16x64. blockIdx.y==4 -> the B/C rows (k in [128,160)).
// ---------------------------------------------------------------------------
__global__ __launch_bounds__(256) void gemm1_tc(const float* __restrict__ x,
                                                const float* __restrict__ w1)
{
    const int b  = blockIdx.z;
    const int m0 = blockIdx.y * 32;     // k-output base
    const int l0 = blockIdx.x * 256;
    const float* xb = x + (size_t)b * DIN * LL;

    __shared__ uint32_t As[32][36];     // [k(d)][m] tf32
    __shared__ uint32_t Bs[32][260];    // [k(d)][l] tf32

    const int tid  = threadIdx.x;
    const int warp = tid >> 5;
    const int lane = tid & 31;
    const int wm   = warp >> 2;         // 0..1 -> m offset 16
    const int wn   = warp & 3;          // 0..3 -> n offset 64
    const int g    = lane >> 2;         // 0..7
    const int tg   = lane & 3;          // 0..3

    float acc[8][4];
#pragma unroll
    for (int nf = 0; nf < 8; nf++)
#pragma unroll
        for (int r = 0; r < 4; r++) acc[nf][r] = 0.f;

    for (int d0 = 0; d0 < DIN; d0 += 32) {
        // A tile: w1[m0+i][d0+j] -> As[j][i]  (transpose, cvt to tf32)
        {
            const int i = tid >> 3;          // 0..31 (m)
            const int j = (tid & 7) * 4;     // 0..28 (k)
            float4 av = *(const float4*)&w1[(size_t)(m0 + i) * DIN + d0 + j];
            As[j + 0][i] = f2tf(av.x);
            As[j + 1][i] = f2tf(av.y);
            As[j + 2][i] = f2tf(av.z);
            As[j + 3][i] = f2tf(av.w);
        }
        // B tile: x[d0+rr][l0+cc] -> Bs[rr][cc]
#pragma unroll
        for (int q = 0; q < 8; q++) {
            const int lin = tid + q * 256;   // 0..2047
            const int rr  = lin >> 6;        // 0..31
            const int cc  = (lin & 63) * 4;  // 0..252
            float4 bv = *(const float4*)&xb[(size_t)(d0 + rr) * LL + l0 + cc];
            uint4 tv = {f2tf(bv.x), f2tf(bv.y), f2tf(bv.z), f2tf(bv.w)};
            *(uint4*)&Bs[rr][cc] = tv;
        }
        __syncthreads();

#pragma unroll
        for (int kk = 0; kk < 32; kk += 8) {
            const uint32_t a0 = As[kk + tg    ][wm * 16 + g];
            const uint32_t a1 = As[kk + tg    ][wm * 16 + g + 8];
            const uint32_t a2 = As[kk + tg + 4][wm * 16 + g];
            const uint32_t a3 = As[kk + tg + 4][wm * 16 + g + 8];
#pragma unroll
            for (int nf = 0; nf < 8; nf++) {
                const int nc = wn * 64 + nf * 8 + g;
                const uint32_t b0 = Bs[kk + tg    ][nc];
                const uint32_t b1 = Bs[kk + tg + 4][nc];
                mma_tf32(acc[nf], a0, a1, a2, a3, b0, b1);
            }
        }
        __syncthreads();
    }

    // Epilogue
    const bool is_bc = (blockIdx.y == 4);   // k in [128,160)
    const int row0 = m0 + wm * 16 + g;
    const int row1 = row0 + 8;
#pragma unroll
    for (int nf = 0; nf < 8; nf++) {
        const int col = l0 + wn * 64 + nf * 8 + 2 * tg;
        if (!is_bc) {
            float2 v0 = {acc[nf][0], acc[nf][1]};
            float2 v1 = {acc[nf][2], acc[nf][3]};
            *(float2*)&g_dt[((size_t)b * RR + row0) * LL + col] = v0;
            *(float2*)&g_dt[((size_t)b * RR + row1) * LL + col] = v1;
        } else {
            const int n0 = row0 - RR, n1 = row1 - RR;
            float* bcb = g_bc + (size_t)b * LL * 32;
            bcb[(size_t)(col    ) * 32 + n0] = acc[nf][0];
            bcb[(size_t)(col + 1) * 32 + n0] = acc[nf][1];
            bcb[(size_t)(col    ) * 32 + n1] = acc[nf][2];
            bcb[(size_t)(col + 1) * 32 + n1] = acc[nf][3];
        }
    }
}

// ---------------------------------------------------------------------------
// GEMM2 (tf32 TC) + softplus: delta[b,d,l] = softplus(sum_r W2[d,r]*dt[b,r,l] + bias[d])
// Block tile 128(M=d) x 128(N=l), K(r)=128 in chunks of 32. 8 warps (4m x 2n),
// warp tile 32x64 (2 m-frags, 8 n-frags).
// ---------------------------------------------------------------------------
__global__ __launch_bounds__(256) void gemm2_tc(const float* __restrict__ w2,
                                                const float* __restrict__ bias)
{
    const int b  = blockIdx.z;
    const int d0 = blockIdx.y * 128;
    const int l0 = blockIdx.x * 128;

    __shared__ uint32_t As[32][132];    // [k(r)][d] tf32
    __shared__ uint32_t Bs[32][132];    // [k(r)][l] tf32

    const int tid  = threadIdx.x;
    const int warp = tid >> 5;
    const int lane = tid & 31;
    const int wmB  = (warp >> 1) * 32;  // m offset
    const int wnB  = (warp & 1) * 64;   // n offset
    const int g    = lane >> 2;
    const int tg   = lane & 3;

    float acc[2][8][4];
#pragma unroll
    for (int mf = 0; mf < 2; mf++)
#pragma unroll
        for (int nf = 0; nf < 8; nf++)
#pragma unroll
            for (int r = 0; r < 4; r++) acc[mf][nf][r] = 0.f;

    for (int r0 = 0; r0 < RR; r0 += 32) {
        // A tile: w2[d0+i][r0+j] -> As[j][i]
#pragma unroll
        for (int q = 0; q < 4; q++) {
            const int lin = tid + q * 256;   // 0..1023
            const int i   = lin >> 3;        // 0..127 (d)
            const int j   = (lin & 7) * 4;   // 0..28  (r)
            float4 av = *(const float4*)&w2[(size_t)(d0 + i) * RR + r0 + j];
            As[j + 0][i] = f2tf(av.x);
            As[j + 1][i] = f2tf(av.y);
            As[j + 2][i] = f2tf(av.z);
            As[j + 3][i] = f2tf(av.w);
        }
        // B tile: g_dt[b][r0+rr][l0+cc] -> Bs[rr][cc]
#pragma unroll
        for (int q = 0; q < 4; q++) {
            const int lin = tid + q * 256;
            const int rr  = lin >> 5;        // 0..31
            const int cc  = (lin & 31) * 4;  // 0..124
            float4 bv = *(const float4*)&g_dt[((size_t)b * RR + r0 + rr) * LL + l0 + cc];
            uint4 tv = {f2tf(bv.x), f2tf(bv.y), f2tf(bv.z), f2tf(bv.w)};
            *(uint4*)&Bs[rr][cc] = tv;
        }
        __syncthreads();

#pragma unroll
        for (int kk = 0; kk < 32; kk += 8) {
            uint32_t a[2][4];
#pragma unroll
            for (int mf = 0; mf < 2; mf++) {
                a[mf][0] = As[kk + tg    ][wmB + mf * 16 + g];
                a[mf][1] = As[kk + tg    ][wmB + mf * 16 + g + 8];
                a[mf][2] = As[kk + tg + 4][wmB + mf * 16 + g];
                a[mf][3] = As[kk + tg + 4][wmB + mf * 16 + g + 8];
            }
#pragma unroll
            for (int nf = 0; nf < 8; nf++) {
                const int nc = wnB + nf * 8 + g;
                const uint32_t b0 = Bs[kk + tg    ][nc];
                const uint32_t b1 = Bs[kk + tg + 4][nc];
#pragma unroll
                for (int mf = 0; mf < 2; mf++)
                    mma_tf32(acc[mf][nf], a[mf][0], a[mf][1], a[mf][2], a[mf][3], b0, b1);
            }
        }
        __syncthreads();
    }

    // Epilogue: bias + softplus, float2 stores
#pragma unroll
    for (int mf = 0; mf < 2; mf++) {
        const int row0 = d0 + wmB + mf * 16 + g;
        const int row1 = row0 + 8;
        const float bi0 = bias[row0];
        const float bi1 = bias[row1];
#pragma unroll
        for (int nf = 0; nf < 8; nf++) {
            const int col = l0 + wnB + nf * 8 + 2 * tg;
            float2 v0 = {softplus_fast(acc[mf][nf][0] + bi0),
                         softplus_fast(acc[mf][nf][1] + bi0)};
            float2 v1 = {softplus_fast(acc[mf][nf][2] + bi1),
                         softplus_fast(acc[mf][nf][3] + bi1)};
            *(float2*)&g_delta[((size_t)b * DIN + row0) * LL + col] = v0;
            *(float2*)&g_delta[((size_t)b * DIN + row1) * LL + col] = v1;
        }
    }
}

// ---------------------------------------------------------------------------
// Scan: one 16-lane group per (b,d). Lane n owns state h[n].
// Reduce-scatter (4 shfl / 4 steps); u*D folded into lane 0's partial.
// ---------------------------------------------------------------------------
__global__ void scan_kernel(const float* __restrict__ x,
                            const float* __restrict__ A_log,
                            const float* __restrict__ Dvec,
                            float* __restrict__ y)
{
    const int gtid  = blockIdx.x * blockDim.x + threadIdx.x;
    const int group = gtid >> 4;
    const int n     = gtid & 15;
    const int b     = group >> 12;
    const int d     = group & 4095;

    const size_t base = ((size_t)b * DIN + d) * LL;
    const float  a    = -__expf(A_log[d * NN + n]);
    const float  dD   = (n == 0) ? Dvec[d] : 0.f;   // folded into reduction
    const float* bcb  = g_bc + (size_t)b * LL * 32;
    // lane n<4 ends holding y for offset jm
    const int jm = ((n & 1) << 1) | ((n >> 1) & 1);

    float h = 0.f;
    for (int l0 = 0; l0 < LL; l0 += 4) {
        const float4 tz = *(const float4*)(g_delta + base + l0);
        const float4 uu = *(const float4*)(x + base + l0);
        const float tj[4] = {tz.x, tz.y, tz.z, tz.w};
        const float uj[4] = {uu.x, uu.y, uu.z, uu.w};
        float p[4];
#pragma unroll
        for (int j = 0; j < 4; j++) {
            const float t  = tj[j];
            const float u  = uj[j];
            const float Bn = bcb[(size_t)(l0 + j) * 32 + n];
            const float Cn = bcb[(size_t)(l0 + j) * 32 + 16 + n];
            const float dA = __expf(t * a);
            h = fmaf(h, dA, (t * u) * Bn);
            p[j] = fmaf(u, dD, h * Cn);
        }
        // reduce-scatter over 16 lanes: 4 shfls for 4 values
        const bool o1 = (n & 1);
        float s0 = o1 ? p[0] : p[2];
        float s1 = o1 ? p[1] : p[3];
        float r0 = __shfl_xor_sync(0xffffffffu, s0, 1);
        float r1 = __shfl_xor_sync(0xffffffffu, s1, 1);
        float u0 = (o1 ? p[2] : p[0]) + r0;
        float u1 = (o1 ? p[3] : p[1]) + r1;
        const bool o2 = (n & 2);
        float s2 = o2 ? u0 : u1;
        float r2 = __shfl_xor_sync(0xffffffffu, s2, 2);
        float v  = (o2 ? u1 : u0) + r2;
        v += __shfl_xor_sync(0xffffffffu, v, 4);
        v += __shfl_xor_sync(0xffffffffu, v, 8);
        if (n < 4) y[base + l0 + jm] = v;
    }
}

// ---------------------------------------------------------------------------
extern "C" void kernel_launch(void* const* d_in, const int* in_sizes, int n_in,
                              void* d_out, int out_size)
{
    const float* x     = (const float*)d_in[0];  // (B, D, L)
    const float* A_log = (const float*)d_in[1];  // (D, N)
    const float* Dvec  = (const float*)d_in[2];  // (D,)
    const float* xpw   = (const float*)d_in[3];  // (160, D)
    const float* dtw   = (const float*)d_in[4];  // (D, R)
    const float* dtb   = (const float*)d_in[5];  // (D,)
    float* y = (float*)d_out;

    {
        dim3 grid(LL / 256, KOUT / 32, B_);   // 16 x 5 x 2 = 160
        gemm1_tc<<<grid, 256>>>(x, xpw);
    }
    {
        dim3 grid(LL / 128, DIN / 128, B_);   // 32 x 32 x 2 = 2048
        gemm2_tc<<<grid, 256>>>(dtw, dtb);
    }
    {
        const int threads = 128;
        const int blocks  = (B_ * DIN * NN) / threads; // 1024
        scan_kernel<<<blocks, threads>>>(x, A_log, Dvec, y);
    }
}

// round 9
// speedup vs baseline: 2.0042x; 1.5429x over previous
#include <cuda_runtime.h>
#include <cuda_bf16.h>
#include <cstdint>

#define B_   2
#define DIN  4096
#define LL   4096
#define NN   16
#define RR   128
#define KOUT 160   // R + 2N

// ---------------- scratch (static __device__ per allocation rules) ----------
__device__ float g_dt[B_ * RR * LL];             // dt_low [b][r][l]            (4 MB)
__device__ float g_bc[B_ * LL * 32];             // B/C transposed [b][l][32]   (1 MB)
__device__ float g_delta[(size_t)B_ * DIN * LL]; // softplus'd delta [b][d][l]  (128 MB)

// ---------------- helpers ---------------------------------------------------
__device__ __forceinline__ uint32_t f2tf(float f) {
    uint32_t u;
    asm("cvt.rna.tf32.f32 %0, %1;" : "=r"(u) : "f"(f));
    return u;
}

__device__ __forceinline__ void mma_tf32(float (&d)[4],
                                         uint32_t a0, uint32_t a1, uint32_t a2, uint32_t a3,
                                         uint32_t b0, uint32_t b1) {
    asm("mma.sync.aligned.m16n8k8.row.col.f32.tf32.tf32.f32 "
        "{%0,%1,%2,%3},{%4,%5,%6,%7},{%8,%9},{%0,%1,%2,%3};"
        : "+f"(d[0]), "+f"(d[1]), "+f"(d[2]), "+f"(d[3])
        : "r"(a0), "r"(a1), "r"(a2), "r"(a3), "r"(b0), "r"(b1));
}

__device__ __forceinline__ float softplus_fast(float z) {
    return fmaxf(z, 0.f) + __logf(1.f + __expf(-fabsf(z)));
}

// ---------------------------------------------------------------------------
// GEMM1 v2 (tf32 TC): xd[b,k,l] = sum_d x[b,d,l] * W1[k,d]
// Tile 32(M=k) x 128(N=l), Kc=32, 128 threads (4 warps: 2m x 2n, warp 16x64).
// Register-staged double buffering. grid (32, 5, 2) = 320 CTAs.
// blockIdx.y==4 -> B/C rows (k in [128,160)).
// ---------------------------------------------------------------------------
__global__ __launch_bounds__(128) void gemm1_tc(const float* __restrict__ x,
                                                const float* __restrict__ w1)
{
    const int b  = blockIdx.z;
    const int m0 = blockIdx.y * 32;
    const int l0 = blockIdx.x * 128;
    const float* xb = x + (size_t)b * DIN * LL;

    __shared__ uint32_t As[32][36];     // [k(d)][m] tf32
    __shared__ uint32_t Bs[32][132];    // [k(d)][l] tf32

    const int tid  = threadIdx.x;
    const int warp = tid >> 5;
    const int lane = tid & 31;
    const int wm   = warp >> 1;         // 0..1 -> m offset 16
    const int wn   = warp & 1;          // 0..1 -> n offset 64
    const int g    = lane >> 2;         // 0..7
    const int tg   = lane & 3;          // 0..3

    const int ai[2] = { (tid)      >> 3, (tid + 128) >> 3 };       // m row 0..31
    const int aj    = (tid & 7) * 4;                               // k col 0..28
    const int br[8] = { tid >> 5, (tid+128)>>5, (tid+256)>>5, (tid+384)>>5,
                        (tid+512)>>5, (tid+640)>>5, (tid+768)>>5, (tid+896)>>5 };
    const int bc    = (tid & 31) * 4;

    float4 sA[2], sB[8];

#pragma unroll
    for (int q = 0; q < 2; q++)
        sA[q] = *(const float4*)&w1[(size_t)(m0 + ai[q]) * DIN + aj];
#pragma unroll
    for (int q = 0; q < 8; q++)
        sB[q] = *(const float4*)&xb[(size_t)br[q] * LL + l0 + bc];

    float acc[8][4];
#pragma unroll
    for (int nf = 0; nf < 8; nf++)
#pragma unroll
        for (int r = 0; r < 4; r++) acc[nf][r] = 0.f;

    for (int d0 = 0; d0 < DIN; d0 += 32) {
#pragma unroll
        for (int q = 0; q < 2; q++) {
            As[aj + 0][ai[q]] = f2tf(sA[q].x);
            As[aj + 1][ai[q]] = f2tf(sA[q].y);
            As[aj + 2][ai[q]] = f2tf(sA[q].z);
            As[aj + 3][ai[q]] = f2tf(sA[q].w);
        }
#pragma unroll
        for (int q = 0; q < 8; q++) {
            uint4 tv = {f2tf(sB[q].x), f2tf(sB[q].y), f2tf(sB[q].z), f2tf(sB[q].w)};
            *(uint4*)&Bs[br[q]][bc] = tv;
        }
        __syncthreads();

        const int dn = d0 + 32;
        if (dn < DIN) {
#pragma unroll
            for (int q = 0; q < 2; q++)
                sA[q] = *(const float4*)&w1[(size_t)(m0 + ai[q]) * DIN + dn + aj];
#pragma unroll
            for (int q = 0; q < 8; q++)
                sB[q] = *(const float4*)&xb[(size_t)(dn + br[q]) * LL + l0 + bc];
        }

#pragma unroll
        for (int kk = 0; kk < 32; kk += 8) {
            const uint32_t a0 = As[kk + tg    ][wm * 16 + g];
            const uint32_t a1 = As[kk + tg    ][wm * 16 + g + 8];
            const uint32_t a2 = As[kk + tg + 4][wm * 16 + g];
            const uint32_t a3 = As[kk + tg + 4][wm * 16 + g + 8];
#pragma unroll
            for (int nf = 0; nf < 8; nf++) {
                const int nc = wn * 64 + nf * 8 + g;
                const uint32_t b0 = Bs[kk + tg    ][nc];
                const uint32_t b1 = Bs[kk + tg + 4][nc];
                mma_tf32(acc[nf], a0, a1, a2, a3, b0, b1);
            }
        }
        __syncthreads();
    }

    const bool is_bc = (blockIdx.y == 4);   // k in [128,160)
    const int row0 = m0 + wm * 16 + g;
    const int row1 = row0 + 8;
#pragma unroll
    for (int nf = 0; nf < 8; nf++) {
        const int col = l0 + wn * 64 + nf * 8 + 2 * tg;
        if (!is_bc) {
            float2 v0 = {acc[nf][0], acc[nf][1]};
            float2 v1 = {acc[nf][2], acc[nf][3]};
            *(float2*)&g_dt[((size_t)b * RR + row0) * LL + col] = v0;
            *(float2*)&g_dt[((size_t)b * RR + row1) * LL + col] = v1;
        } else {
            const int n0 = row0 - RR, n1 = row1 - RR;
            float* bcb = g_bc + (size_t)b * LL * 32;
            bcb[(size_t)(col    ) * 32 + n0] = acc[nf][0];
            bcb[(size_t)(col + 1) * 32 + n0] = acc[nf][1];
            bcb[(size_t)(col    ) * 32 + n1] = acc[nf][2];
            bcb[(size_t)(col + 1) * 32 + n1] = acc[nf][3];
        }
    }
}

// ---------------------------------------------------------------------------
// GEMM2 (tf32 TC) + softplus: delta[b,d,l] = softplus(sum_r W2[d,r]*dt[b,r,l] + bias[d])
// Block tile 128(M=d) x 128(N=l), K(r)=128 in chunks of 32. 8 warps (4m x 2n).
// Register-staged double buffering across the 4 k-chunks.
// ---------------------------------------------------------------------------
__global__ __launch_bounds__(256) void gemm2_tc(const float* __restrict__ w2,
                                                const float* __restrict__ bias)
{
    const int b  = blockIdx.z;
    const int d0 = blockIdx.y * 128;
    const int l0 = blockIdx.x * 128;

    __shared__ uint32_t As[32][132];    // [k(r)][d] tf32
    __shared__ uint32_t Bs[32][132];    // [k(r)][l] tf32

    const int tid  = threadIdx.x;
    const int warp = tid >> 5;
    const int lane = tid & 31;
    const int wmB  = (warp >> 1) * 32;
    const int wnB  = (warp & 1) * 64;
    const int g    = lane >> 2;
    const int tg   = lane & 3;

    // fixed load coords: A -> 4 float4 (rows of w2), B -> 4 float4 (rows of dt)
    const int Ai[4] = { tid >> 3, (tid+256)>>3, (tid+512)>>3, (tid+768)>>3 };  // d 0..127
    const int Aj    = (tid & 7) * 4;                                           // r 0..28
    const int Br[4] = { tid >> 5, (tid+256)>>5, (tid+512)>>5, (tid+768)>>5 };  // r 0..31
    const int Bc    = (tid & 31) * 4;                                          // l 0..124

    float4 sA[4], sB[4];
#pragma unroll
    for (int q = 0; q < 4; q++) {
        sA[q] = *(const float4*)&w2[(size_t)(d0 + Ai[q]) * RR + Aj];
        sB[q] = *(const float4*)&g_dt[((size_t)b * RR + Br[q]) * LL + l0 + Bc];
    }

    float acc[2][8][4];
#pragma unroll
    for (int mf = 0; mf < 2; mf++)
#pragma unroll
        for (int nf = 0; nf < 8; nf++)
#pragma unroll
            for (int r = 0; r < 4; r++) acc[mf][nf][r] = 0.f;

    for (int r0 = 0; r0 < RR; r0 += 32) {
#pragma unroll
        for (int q = 0; q < 4; q++) {
            As[Aj + 0][Ai[q]] = f2tf(sA[q].x);
            As[Aj + 1][Ai[q]] = f2tf(sA[q].y);
            As[Aj + 2][Ai[q]] = f2tf(sA[q].z);
            As[Aj + 3][Ai[q]] = f2tf(sA[q].w);
            uint4 tv = {f2tf(sB[q].x), f2tf(sB[q].y), f2tf(sB[q].z), f2tf(sB[q].w)};
            *(uint4*)&Bs[Br[q]][Bc] = tv;
        }
        __syncthreads();

        const int rn = r0 + 32;
        if (rn < RR) {
#pragma unroll
            for (int q = 0; q < 4; q++) {
                sA[q] = *(const float4*)&w2[(size_t)(d0 + Ai[q]) * RR + rn + Aj];
                sB[q] = *(const float4*)&g_dt[((size_t)b * RR + rn + Br[q]) * LL + l0 + Bc];
            }
        }

#pragma unroll
        for (int kk = 0; kk < 32; kk += 8) {
            uint32_t a[2][4];
#pragma unroll
            for (int mf = 0; mf < 2; mf++) {
                a[mf][0] = As[kk + tg    ][wmB + mf * 16 + g];
                a[mf][1] = As[kk + tg    ][wmB + mf * 16 + g + 8];
                a[mf][2] = As[kk + tg + 4][wmB + mf * 16 + g];
                a[mf][3] = As[kk + tg + 4][wmB + mf * 16 + g + 8];
            }
#pragma unroll
            for (int nf = 0; nf < 8; nf++) {
                const int nc = wnB + nf * 8 + g;
                const uint32_t b0 = Bs[kk + tg    ][nc];
                const uint32_t b1 = Bs[kk + tg + 4][nc];
#pragma unroll
                for (int mf = 0; mf < 2; mf++)
                    mma_tf32(acc[mf][nf], a[mf][0], a[mf][1], a[mf][2], a[mf][3], b0, b1);
            }
        }
        __syncthreads();
    }

#pragma unroll
    for (int mf = 0; mf < 2; mf++) {
        const int row0 = d0 + wmB + mf * 16 + g;
        const int row1 = row0 + 8;
        const float bi0 = bias[row0];
        const float bi1 = bias[row1];
#pragma unroll
        for (int nf = 0; nf < 8; nf++) {
            const int col = l0 + wnB + nf * 8 + 2 * tg;
            float2 v0 = {softplus_fast(acc[mf][nf][0] + bi0),
                         softplus_fast(acc[mf][nf][1] + bi0)};
            float2 v1 = {softplus_fast(acc[mf][nf][2] + bi1),
                         softplus_fast(acc[mf][nf][3] + bi1)};
            *(float2*)&g_delta[((size_t)b * DIN + row0) * LL + col] = v0;
            *(float2*)&g_delta[((size_t)b * DIN + row1) * LL + col] = v1;
        }
    }
}

// ---------------------------------------------------------------------------
// Scan v2: 256 threads = 16 groups (16 consecutive d, same b). Lane n owns h[n].
// Chunks of 32 timesteps staged in smem (bc + delta + x), register-prefetched.
// Inner loop is pure LDS (broadcast) + exp/fma + 4-shfl reduce-scatter.
// ---------------------------------------------------------------------------
#define CH 32
__global__ __launch_bounds__(256) void scan_kernel(const float* __restrict__ x,
                                                   const float* __restrict__ A_log,
                                                   const float* __restrict__ Dvec,
                                                   float* __restrict__ y)
{
    __shared__ float del_s[16][CH];
    __shared__ float x_s[16][CH];
    __shared__ float bc_s[CH * 32];

    const int tid = threadIdx.x;
    const int lg  = tid >> 4;            // local group 0..15
    const int n   = tid & 15;
    const int gb  = blockIdx.x * 16;     // global group base
    const int b   = gb >> 12;
    const int d   = (gb & 4095) + lg;

    const size_t base = ((size_t)b * DIN + d) * LL;
    const float  a    = -__expf(A_log[d * NN + n]);
    const float  dD   = (n == 0) ? Dvec[d] : 0.f;
    const float* bcb  = g_bc + (size_t)b * LL * 32;
    const int jm = ((n & 1) << 1) | ((n >> 1) & 1);

    // staging roles: all threads load bc; tid<128 -> delta rows, else -> x rows
    const int sg = (tid & 127) >> 3;           // staged group 0..15
    const int sq = (tid & 7) * 4;              // offset within chunk
    const size_t srow = ((size_t)b * DIN + (gb & 4095) + sg) * LL;
    const float* sptr = (tid < 128 ? (const float*)g_delta : x) + srow;

    float4 rbc = *(const float4*)&bcb[(size_t)0 * 32 + tid * 4];
    float4 rdu = *(const float4*)&sptr[sq];

    float h = 0.f;
    for (int l0 = 0; l0 < LL; l0 += CH) {
        // commit staged chunk
        *(float4*)&bc_s[tid * 4] = rbc;
        if (tid < 128) *(float4*)&del_s[sg][sq] = rdu;
        else           *(float4*)&x_s[sg][sq]   = rdu;
        __syncthreads();

        // prefetch next chunk
        const int ln = l0 + CH;
        if (ln < LL) {
            rbc = *(const float4*)&bcb[(size_t)ln * 32 + tid * 4];
            rdu = *(const float4*)&sptr[ln + sq];
        }

#pragma unroll
        for (int jj = 0; jj < CH; jj += 4) {
            const float4 tz = *(const float4*)&del_s[lg][jj];
            const float4 uu = *(const float4*)&x_s[lg][jj];
            const float tj[4] = {tz.x, tz.y, tz.z, tz.w};
            const float uj[4] = {uu.x, uu.y, uu.z, uu.w};
            float p[4];
#pragma unroll
            for (int j = 0; j < 4; j++) {
                const float t  = tj[j];
                const float u  = uj[j];
                const float Bn = bc_s[(jj + j) * 32 + n];
                const float Cn = bc_s[(jj + j) * 32 + 16 + n];
                const float dA = __expf(t * a);
                h = fmaf(h, dA, (t * u) * Bn);
                p[j] = fmaf(u, dD, h * Cn);
            }
            // reduce-scatter over 16 lanes: 4 shfls for 4 values
            const bool o1 = (n & 1);
            float s0 = o1 ? p[0] : p[2];
            float s1 = o1 ? p[1] : p[3];
            float r0 = __shfl_xor_sync(0xffffffffu, s0, 1);
            float r1 = __shfl_xor_sync(0xffffffffu, s1, 1);
            float u0 = (o1 ? p[2] : p[0]) + r0;
            float u1 = (o1 ? p[3] : p[1]) + r1;
            const bool o2 = (n & 2);
            float s2 = o2 ? u0 : u1;
            float r2 = __shfl_xor_sync(0xffffffffu, s2, 2);
            float v  = (o2 ? u1 : u0) + r2;
            v += __shfl_xor_sync(0xffffffffu, v, 4);
            v += __shfl_xor_sync(0xffffffffu, v, 8);
            if (n < 4) y[base + l0 + jj + jm] = v;
        }
        __syncthreads();
    }
}

// ---------------------------------------------------------------------------
extern "C" void kernel_launch(void* const* d_in, const int* in_sizes, int n_in,
                              void* d_out, int out_size)
{
    const float* x     = (const float*)d_in[0];  // (B, D, L)
    const float* A_log = (const float*)d_in[1];  // (D, N)
    const float* Dvec  = (const float*)d_in[2];  // (D,)
    const float* xpw   = (const float*)d_in[3];  // (160, D)
    const float* dtw   = (const float*)d_in[4];  // (D, R)
    const float* dtb   = (const float*)d_in[5];  // (D,)
    float* y = (float*)d_out;

    {
        dim3 grid(LL / 128, KOUT / 32, B_);   // 32 x 5 x 2 = 320
        gemm1_tc<<<grid, 128>>>(x, xpw);
    }
    {
        dim3 grid(LL / 128, DIN / 128, B_);   // 32 x 32 x 2 = 2048
        gemm2_tc<<<grid, 256>>>(dtw, dtb);
    }
    {
        const int blocks = (B_ * DIN) / 16;   // 512 blocks of 16 groups
        scan_kernel<<<blocks, 256>>>(x, A_log, Dvec, y);
    }
}